// round 1
// baseline (speedup 1.0000x reference)
#include <cuda_runtime.h>
#include <cstdint>

#define HCHUNK 64          // hidden rows per chunk
#define PADF   66          // floats per feature row in smem (8B-aligned, conflict-free)
#define NNZP   32          // features per position
#define MAX_B  16384
#define MAX_NNZ (MAX_B * NNZP)
#define POSBLKS 18         // position blocks (18 * 8 chunks = 144 CTAs <= 148 SMs)

// scratch (static __device__ allocations are allowed)
__device__ uint2 g_packed[2][MAX_NNZ];        // (byte_offset, value_bits) per nnz per side
__device__ float g_partials[16 * MAX_B];      // [chunk*2+side][B] partial output dots
__device__ int   g_is64;                      // index dtype flag

// ---------------------------------------------------------------------------
// Detect whether indices are int64 or int32.
// Interpreted as int32 words, odd words of the batch_row region are:
//   int64 data -> high halves of small ints -> all zero
//   int32 data -> batch_row values (i/32)   -> nonzero for word index >= 64
__global__ void detect_kernel(const int* __restrict__ words) {
    int nz = 0;
    #pragma unroll
    for (int k = 1; k <= 32; k++) nz |= words[64 * k + 33];
    g_is64 = (nz == 0) ? 1 : 0;
}

// ---------------------------------------------------------------------------
// Pack (feature -> smem byte offset, value) pairs for both sides.
__global__ void pack_kernel(const void* __restrict__ stm_idx,
                            const void* __restrict__ nstm_idx,
                            const float* __restrict__ stm_val,
                            const float* __restrict__ nstm_val,
                            int nnz) {
    int i = blockIdx.x * blockDim.x + threadIdx.x;
    if (i >= 2 * nnz) return;
    int side = (i >= nnz) ? 1 : 0;
    int j = side ? (i - nnz) : i;
    const void* idx = side ? nstm_idx : stm_idx;
    const float* val = side ? nstm_val : stm_val;
    int f;
    if (g_is64) {
        // features live in row 1: element offset nnz
        f = (int)((const long long*)idx)[(size_t)nnz + j];
    } else {
        f = ((const int*)idx)[(size_t)nnz + j];
    }
    g_packed[side][j] = make_uint2((unsigned)(f * (PADF * 4)), __float_as_uint(val[j]));
}

// ---------------------------------------------------------------------------
// Main feature-transformer kernel. grid = (POSBLKS, H/HCHUNK), block = 512.
// Each CTA caches W_ft[h0:h0+64, :] transposed in smem (feature-major, padded),
// then each warp processes (position, side) items: accumulate 64 hidden units
// (2 per lane), clip, dot with W_out segment, warp-reduce, store partial.
extern __shared__ float s_w[];

__global__ __launch_bounds__(512, 1)
void ft_kernel(const float* __restrict__ W_ft,
               const float* __restrict__ b_ft,
               const float* __restrict__ W_out,
               int B, int F, int H, int pos_per_block) {
    const int chunk = blockIdx.y;
    const int h0 = chunk * HCHUNK;

    // Load tile: s_w[f*PADF + j] = W_ft[h0+j, f]. Coalesced LDG; STS stride 66
    // floats -> 2-way bank conflict (tile load is a tiny fraction of runtime).
    for (int j = 0; j < HCHUNK; j++) {
        for (int f = threadIdx.x; f < F; f += blockDim.x) {
            s_w[f * PADF + j] = W_ft[(size_t)(h0 + j) * F + f];
        }
    }
    __syncthreads();

    const int lane  = threadIdx.x & 31;
    const int warp  = threadIdx.x >> 5;
    const int nwarp = blockDim.x >> 5;

    const float2 bv  = *(const float2*)(b_ft  + h0 + 2 * lane);
    const float2 wo0 = *(const float2*)(W_out + h0 + 2 * lane);
    const float2 wo1 = *(const float2*)(W_out + H + h0 + 2 * lane);

    const char* sb = (const char*)s_w;
    const int p0 = blockIdx.x * pos_per_block;
    const int p1 = min(p0 + pos_per_block, B);
    const int nitems = (p1 - p0) * 2;

    for (int it = warp; it < nitems; it += nwarp) {
        const int p = p0 + (it >> 1);
        const int side = it & 1;
        const uint4* pk = (const uint4*)(&g_packed[side][(size_t)p * NNZP]);

        float ax = 0.f, ay = 0.f;
        #pragma unroll
        for (int kk = 0; kk < NNZP / 2; kk++) {
            const uint4 pr = pk[kk];          // same addr across warp -> broadcast
            float2 w;
            w = *(const float2*)(sb + pr.x + 8 * lane);
            ax = fmaf(__uint_as_float(pr.y), w.x, ax);
            ay = fmaf(__uint_as_float(pr.y), w.y, ay);
            w = *(const float2*)(sb + pr.z + 8 * lane);
            ax = fmaf(__uint_as_float(pr.w), w.x, ax);
            ay = fmaf(__uint_as_float(pr.w), w.y, ay);
        }

        const float hx = __saturatef(ax + bv.x);
        const float hy = __saturatef(ay + bv.y);
        const float2 wo = side ? wo1 : wo0;
        float part = hx * wo.x + hy * wo.y;
        #pragma unroll
        for (int o = 16; o; o >>= 1)
            part += __shfl_xor_sync(0xFFFFFFFFu, part, o);
        if (lane == 0)
            g_partials[(size_t)(chunk * 2 + side) * B + p] = part;
    }
}

// ---------------------------------------------------------------------------
// Epilogue: sum partials + b_out, sigmoid.
__global__ void out_kernel(const float* __restrict__ b_out,
                           float* __restrict__ out, int B, int nparts) {
    int p = blockIdx.x * blockDim.x + threadIdx.x;
    if (p >= B) return;
    float s = b_out[0];
    for (int i = 0; i < nparts; i++) s += g_partials[(size_t)i * B + p];
    out[p] = 1.f / (1.f + expf(-s));
}

// ---------------------------------------------------------------------------
extern "C" void kernel_launch(void* const* d_in, const int* in_sizes, int n_in,
                              void* d_out, int out_size) {
    // Input order: stm_indices, nstm_indices, stm_values, nstm_values,
    //              [batch_size], W_ft, b_ft, W_out, b_out
    const void* stm_idx  = d_in[0];
    const void* nstm_idx = d_in[1];
    const float* stm_val  = (const float*)d_in[2];
    const float* nstm_val = (const float*)d_in[3];
    int w = 4;
    if (n_in >= 9 && in_sizes[4] == 1) w = 5;   // skip batch_size scalar
    const float* W_ft  = (const float*)d_in[w];
    const float* b_ft  = (const float*)d_in[w + 1];
    const float* W_out = (const float*)d_in[w + 2];
    const float* b_out = (const float*)d_in[w + 3];

    const int B   = out_size;                   // output is [B, 1] float32
    const int H   = in_sizes[w + 1];            // b_ft size
    const int F   = in_sizes[w] / H;
    const int nnz = in_sizes[2];                // stm_values count

    const int smem_bytes = F * PADF * (int)sizeof(float);
    cudaFuncSetAttribute(ft_kernel, cudaFuncAttributeMaxDynamicSharedMemorySize,
                         smem_bytes);

    detect_kernel<<<1, 1>>>((const int*)stm_idx);

    {
        int total = 2 * nnz;
        pack_kernel<<<(total + 255) / 256, 256>>>(stm_idx, nstm_idx,
                                                  stm_val, nstm_val, nnz);
    }

    {
        const int nchunks = H / HCHUNK;             // 8
        const int ppb = (B + POSBLKS - 1) / POSBLKS;
        dim3 grid(POSBLKS, nchunks);
        ft_kernel<<<grid, 512, smem_bytes>>>(W_ft, b_ft, W_out, B, F, H, ppb);
    }

    {
        const int nparts = (H / HCHUNK) * 2;        // 16
        out_kernel<<<(B + 255) / 256, 256>>>(b_out, (float*)d_out, B, nparts);
    }
}

// round 2
// speedup vs baseline: 1.7916x; 1.7916x over previous
#include <cuda_runtime.h>
#include <cuda_fp16.h>
#include <cstdint>

#define HCHUNK 128            // hidden units per chunk (H=512 -> 4 chunks)
#define PADH   132            // halves per feature row (264B, keeps 8B align, cheap STS)
#define NNZP   32             // features per position
#define MAX_B  16384
#define MAX_NNZ (MAX_B * NNZP)
#define POSBLKS 37            // 37 * 4 chunks = 148 CTAs = 1 per SM
#define TILE_P  32            // positions staged per smem pair tile

#define WBYTES   (768 * PADH * 2)              // fp16 weight tile bytes (202,752)
#define PBYTES   (2 * TILE_P * NNZP * 8)       // staged pair bytes (16,384)

// scratch (__device__ globals: allocation-free)
__device__ uint2 g_packed[2][MAX_NNZ];        // (byte_offset, value_bits) per nnz per side
__device__ float g_partials[8 * MAX_B];       // [chunk*2+side][B]
__device__ int   g_is64;

// ---------------------------------------------------------------------------
// int64 vs int32 index detection (row 0 = batch_row, values < 2^31):
// as int32 words, odd words are 0 iff data is int64.
__global__ void detect_kernel(const int* __restrict__ words) {
    int nz = 0;
    #pragma unroll
    for (int k = 1; k <= 32; k++) nz |= words[64 * k + 33];
    g_is64 = (nz == 0) ? 1 : 0;
}

// ---------------------------------------------------------------------------
// Pack (feature -> smem byte offset, value) pairs for both sides.
__global__ void pack_kernel(const void* __restrict__ stm_idx,
                            const void* __restrict__ nstm_idx,
                            const float* __restrict__ stm_val,
                            const float* __restrict__ nstm_val,
                            int nnz) {
    int i = blockIdx.x * blockDim.x + threadIdx.x;
    if (i >= 2 * nnz) return;
    int side = (i >= nnz) ? 1 : 0;
    int j = side ? (i - nnz) : i;
    const void* idx = side ? nstm_idx : stm_idx;
    const float* val = side ? nstm_val : stm_val;
    int f;
    if (g_is64) {
        f = (int)((const long long*)idx)[(size_t)nnz + j];   // row 1 = features
    } else {
        f = ((const int*)idx)[(size_t)nnz + j];
    }
    g_packed[side][j] = make_uint2((unsigned)(f * (PADH * 2)), __float_as_uint(val[j]));
}

// ---------------------------------------------------------------------------
// Feature transformer. grid = (POSBLKS, 4), block = 512, 1 CTA/SM.
// smem: fp16 weight tile [768 feat][128 units] (stride PADH halves) + pair tile.
extern __shared__ char s_raw[];

__global__ __launch_bounds__(512, 1)
void ft_kernel(const float* __restrict__ W_ft,
               const float* __restrict__ b_ft,
               const float* __restrict__ W_out,
               int B, int F, int H, int ppb) {
    __half* s_w = (__half*)s_raw;
    uint2*  s_pairs = (uint2*)(s_raw + WBYTES);

    const int chunk = blockIdx.y;
    const int h0 = chunk * HCHUNK;

    // Load tile: s_w[f*PADH + j] = half(W_ft[h0+j, f]). half2 stores (j, j+1).
    for (int idx = threadIdx.x; idx < F * (HCHUNK / 2); idx += blockDim.x) {
        int f  = idx % F;                  // consecutive threads -> coalesced LDG
        int jp = idx / F;
        float v0 = W_ft[(size_t)(h0 + 2 * jp) * F + f];
        float v1 = W_ft[(size_t)(h0 + 2 * jp + 1) * F + f];
        *(__half2*)(s_w + (size_t)f * PADH + 2 * jp) = __floats2half2_rn(v0, v1);
    }

    const int lane = threadIdx.x & 31;
    const int warp = threadIdx.x >> 5;

    const float4 bv  = *(const float4*)(b_ft  + h0 + 4 * lane);
    const float4 wo0 = *(const float4*)(W_out + h0 + 4 * lane);
    const float4 wo1 = *(const float4*)(W_out + H + h0 + 4 * lane);

    const char* sb = (const char*)s_w;
    const int p0 = blockIdx.x * ppb;
    const int p1 = min(p0 + ppb, B);

    for (int pt = p0; pt < p1; pt += TILE_P) {
        const int tp = min(TILE_P, p1 - pt);
        __syncthreads();   // previous tile fully consumed (also covers tile load, 1st iter)
        {   // stage pair lists for this position tile (both sides), coalesced
            const int nvec = tp * (NNZP / 2);            // uint4 per side
            const uint4* src0 = (const uint4*)(g_packed[0] + (size_t)pt * NNZP);
            const uint4* src1 = (const uint4*)(g_packed[1] + (size_t)pt * NNZP);
            uint4* dst = (uint4*)s_pairs;
            for (int i = threadIdx.x; i < nvec; i += blockDim.x) {
                dst[i] = src0[i];
                dst[TILE_P * (NNZP / 2) + i] = src1[i];
            }
        }
        __syncthreads();

        const int nit = tp * 2;
        for (int it = warp; it < nit; it += 16) {
            const int lp = it >> 1;
            const int side = it & 1;
            const uint4* pk = (const uint4*)s_pairs
                              + side * (TILE_P * (NNZP / 2)) + lp * (NNZP / 2);

            float ax = 0.f, ay = 0.f, az = 0.f, aw = 0.f;
            #pragma unroll
            for (int kk = 0; kk < NNZP / 2; kk++) {
                const uint4 pr = pk[kk];                 // broadcast LDS.128
                {
                    uint2 w = *(const uint2*)(sb + pr.x + 8 * lane);
                    float2 w01 = __half22float2(*(__half2*)&w.x);
                    float2 w23 = __half22float2(*(__half2*)&w.y);
                    float v = __uint_as_float(pr.y);
                    ax = fmaf(v, w01.x, ax); ay = fmaf(v, w01.y, ay);
                    az = fmaf(v, w23.x, az); aw = fmaf(v, w23.y, aw);
                }
                {
                    uint2 w = *(const uint2*)(sb + pr.z + 8 * lane);
                    float2 w01 = __half22float2(*(__half2*)&w.x);
                    float2 w23 = __half22float2(*(__half2*)&w.y);
                    float v = __uint_as_float(pr.w);
                    ax = fmaf(v, w01.x, ax); ay = fmaf(v, w01.y, ay);
                    az = fmaf(v, w23.x, az); aw = fmaf(v, w23.y, aw);
                }
            }

            const float4 wo = side ? wo1 : wo0;
            float part = __saturatef(ax + bv.x) * wo.x
                       + __saturatef(ay + bv.y) * wo.y
                       + __saturatef(az + bv.z) * wo.z
                       + __saturatef(aw + bv.w) * wo.w;
            #pragma unroll
            for (int o = 16; o; o >>= 1)
                part += __shfl_xor_sync(0xFFFFFFFFu, part, o);
            if (lane == 0)
                g_partials[(size_t)(chunk * 2 + side) * B + pt + lp] = part;
        }
    }
}

// ---------------------------------------------------------------------------
__global__ void out_kernel(const float* __restrict__ b_out,
                           float* __restrict__ out, int B, int nparts) {
    int p = blockIdx.x * blockDim.x + threadIdx.x;
    if (p >= B) return;
    float s = b_out[0];
    for (int i = 0; i < nparts; i++) s += g_partials[(size_t)i * B + p];
    out[p] = 1.f / (1.f + expf(-s));
}

// ---------------------------------------------------------------------------
extern "C" void kernel_launch(void* const* d_in, const int* in_sizes, int n_in,
                              void* d_out, int out_size) {
    const void* stm_idx  = d_in[0];
    const void* nstm_idx = d_in[1];
    const float* stm_val  = (const float*)d_in[2];
    const float* nstm_val = (const float*)d_in[3];
    int w = 4;
    if (n_in >= 9 && in_sizes[4] == 1) w = 5;   // skip batch_size scalar
    const float* W_ft  = (const float*)d_in[w];
    const float* b_ft  = (const float*)d_in[w + 1];
    const float* W_out = (const float*)d_in[w + 2];
    const float* b_out = (const float*)d_in[w + 3];

    const int B   = out_size;
    const int H   = in_sizes[w + 1];
    const int F   = in_sizes[w] / H;
    const int nnz = in_sizes[2];

    const int smem_bytes = WBYTES + PBYTES;     // 219,136 B
    cudaFuncSetAttribute(ft_kernel, cudaFuncAttributeMaxDynamicSharedMemorySize,
                         smem_bytes);

    detect_kernel<<<1, 1>>>((const int*)stm_idx);

    {
        int total = 2 * nnz;
        pack_kernel<<<(total + 255) / 256, 256>>>(stm_idx, nstm_idx,
                                                  stm_val, nstm_val, nnz);
    }

    {
        const int nchunks = H / HCHUNK;                 // 4
        const int ppb = (B + POSBLKS - 1) / POSBLKS;    // 443
        dim3 grid(POSBLKS, nchunks);
        ft_kernel<<<grid, 512, smem_bytes>>>(W_ft, b_ft, W_out, B, F, H, ppb);
    }

    {
        const int nparts = (H / HCHUNK) * 2;            // 8
        out_kernel<<<(B + 255) / 256, 256>>>(b_out, (float*)d_out, B, nparts);
    }
}

// round 3
// speedup vs baseline: 1.8803x; 1.0495x over previous
#include <cuda_runtime.h>
#include <cuda_fp16.h>
#include <cstdint>

#define HCHUNK 128            // hidden units per chunk (H=512 -> 4 chunks)
#define PADH   132            // halves per feature row (264B, 8B-aligned)
#define NNZP   32             // features per position
#define MAX_B  16384
#define MAX_NNZ (MAX_B * NNZP)
#define POSBLKS 37            // 37 * 4 chunks = 148 CTAs = 1 per SM
#define TILE_P  32            // positions staged per smem pair tile

#define WBYTES   (768 * PADH * 2)              // fp16 weight tile bytes (202,752)
#define PBYTES   (2 * TILE_P * NNZP * 8)       // staged pair bytes (16,384)

// scratch (__device__ globals: allocation-free)
__device__ uint2 g_packed[2][MAX_NNZ];  // (byte_offset, value as half2(v,v)) per nnz/side
__device__ float g_partials[8 * MAX_B]; // [chunk*2+side][B]

// ---------------------------------------------------------------------------
// Pack (feature -> smem byte offset, value as half2) pairs for both sides.
// int64-vs-int32 index detection is done redundantly per block (L2-hit reads):
// viewing batch_row as int32 words, odd words are all 0 iff data is int64.
__global__ void pack_kernel(const void* __restrict__ stm_idx,
                            const void* __restrict__ nstm_idx,
                            const float* __restrict__ stm_val,
                            const float* __restrict__ nstm_val,
                            int nnz) {
    __shared__ int s_is64;
    if (threadIdx.x == 0) {
        const int* words = (const int*)stm_idx;
        int nz = 0;
        #pragma unroll
        for (int k = 1; k <= 32; k++) nz |= words[64 * k + 33];
        s_is64 = (nz == 0) ? 1 : 0;
    }
    __syncthreads();
    const int is64 = s_is64;

    int i = blockIdx.x * blockDim.x + threadIdx.x;
    if (i >= 2 * nnz) return;
    int side = (i >= nnz) ? 1 : 0;
    int j = side ? (i - nnz) : i;
    const void* idx = side ? nstm_idx : stm_idx;
    const float* val = side ? nstm_val : stm_val;
    int f;
    if (is64) {
        f = (int)((const long long*)idx)[(size_t)nnz + j];   // row 1 = features
    } else {
        f = ((const int*)idx)[(size_t)nnz + j];
    }
    unsigned hb = (unsigned)__half_as_ushort(__float2half(val[j]));
    g_packed[side][j] = make_uint2((unsigned)(f * (PADH * 2)), hb | (hb << 16));
}

// ---------------------------------------------------------------------------
// Feature transformer. grid = (POSBLKS, 4), block = 512, 1 CTA/SM.
// smem: fp16 weight tile [768 feat][128 units] (stride PADH halves) + pair tile.
// Lane owns 4 hidden units, accumulated in two half2 registers via HFMA2.
extern __shared__ char s_raw[];

__global__ __launch_bounds__(512, 1)
void ft_kernel(const float* __restrict__ W_ft,
               const float* __restrict__ b_ft,
               const float* __restrict__ W_out,
               int B, int F, int H, int ppb) {
    __half* s_w = (__half*)s_raw;
    uint2*  s_pairs = (uint2*)(s_raw + WBYTES);

    const int chunk = blockIdx.y;
    const int h0 = chunk * HCHUNK;

    // Load tile: s_w[f*PADH + j] = half(W_ft[h0+j, f]).
    for (int idx = threadIdx.x; idx < F * (HCHUNK / 2); idx += blockDim.x) {
        int f  = idx % F;                  // consecutive threads -> coalesced LDG
        int jp = idx / F;
        float v0 = W_ft[(size_t)(h0 + 2 * jp) * F + f];
        float v1 = W_ft[(size_t)(h0 + 2 * jp + 1) * F + f];
        *(__half2*)(s_w + (size_t)f * PADH + 2 * jp) = __floats2half2_rn(v0, v1);
    }

    const int lane = threadIdx.x & 31;
    const int warp = threadIdx.x >> 5;

    const float4 bv  = *(const float4*)(b_ft  + h0 + 4 * lane);
    const float4 wo0 = *(const float4*)(W_out + h0 + 4 * lane);
    const float4 wo1 = *(const float4*)(W_out + H + h0 + 4 * lane);

    const char* sb = (const char*)s_w;
    const int p0 = blockIdx.x * ppb;
    const int p1 = min(p0 + ppb, B);

    for (int pt = p0; pt < p1; pt += TILE_P) {
        const int tp = min(TILE_P, p1 - pt);
        __syncthreads();   // previous tile consumed (covers tile load on 1st iter)
        {   // stage pair lists for this position tile (both sides), coalesced
            const int nvec = tp * (NNZP / 2);            // uint4 per side
            const uint4* src0 = (const uint4*)(g_packed[0] + (size_t)pt * NNZP);
            const uint4* src1 = (const uint4*)(g_packed[1] + (size_t)pt * NNZP);
            uint4* dst = (uint4*)s_pairs;
            for (int i = threadIdx.x; i < nvec; i += blockDim.x) {
                dst[i] = src0[i];
                dst[TILE_P * (NNZP / 2) + i] = src1[i];
            }
        }
        __syncthreads();

        const int nit = tp * 2;
        for (int it = warp; it < nit; it += 16) {
            const int lp = it >> 1;
            const int side = it & 1;
            const uint4* pk = (const uint4*)s_pairs
                              + side * (TILE_P * (NNZP / 2)) + lp * (NNZP / 2);

            __half2 a01 = __float2half2_rn(0.f);
            __half2 a23 = __float2half2_rn(0.f);
            #pragma unroll
            for (int kk = 0; kk < NNZP / 2; kk++) {
                const uint4 pr = pk[kk];                 // broadcast LDS.128
                {
                    const __half2 v = *(const __half2*)&pr.y;
                    uint2 w = *(const uint2*)(sb + pr.x + 8 * lane);
                    a01 = __hfma2(v, *(const __half2*)&w.x, a01);
                    a23 = __hfma2(v, *(const __half2*)&w.y, a23);
                }
                {
                    const __half2 v = *(const __half2*)&pr.w;
                    uint2 w = *(const uint2*)(sb + pr.z + 8 * lane);
                    a01 = __hfma2(v, *(const __half2*)&w.x, a01);
                    a23 = __hfma2(v, *(const __half2*)&w.y, a23);
                }
            }

            const float2 f01 = __half22float2(a01);
            const float2 f23 = __half22float2(a23);
            const float4 wo = side ? wo1 : wo0;
            float part = __saturatef(f01.x + bv.x) * wo.x
                       + __saturatef(f01.y + bv.y) * wo.y
                       + __saturatef(f23.x + bv.z) * wo.z
                       + __saturatef(f23.y + bv.w) * wo.w;
            #pragma unroll
            for (int o = 16; o; o >>= 1)
                part += __shfl_xor_sync(0xFFFFFFFFu, part, o);
            if (lane == 0)
                g_partials[(size_t)(chunk * 2 + side) * B + pt + lp] = part;
        }
    }
}

// ---------------------------------------------------------------------------
__global__ void out_kernel(const float* __restrict__ b_out,
                           float* __restrict__ out, int B, int nparts) {
    int p = blockIdx.x * blockDim.x + threadIdx.x;
    if (p >= B) return;
    float s = b_out[0];
    #pragma unroll 8
    for (int i = 0; i < nparts; i++) s += g_partials[(size_t)i * B + p];
    out[p] = 1.f / (1.f + expf(-s));
}

// ---------------------------------------------------------------------------
extern "C" void kernel_launch(void* const* d_in, const int* in_sizes, int n_in,
                              void* d_out, int out_size) {
    const void* stm_idx  = d_in[0];
    const void* nstm_idx = d_in[1];
    const float* stm_val  = (const float*)d_in[2];
    const float* nstm_val = (const float*)d_in[3];
    int w = 4;
    if (n_in >= 9 && in_sizes[4] == 1) w = 5;   // skip batch_size scalar
    const float* W_ft  = (const float*)d_in[w];
    const float* b_ft  = (const float*)d_in[w + 1];
    const float* W_out = (const float*)d_in[w + 2];
    const float* b_out = (const float*)d_in[w + 3];

    const int B   = out_size;
    const int H   = in_sizes[w + 1];
    const int F   = in_sizes[w] / H;
    const int nnz = in_sizes[2];

    const int smem_bytes = WBYTES + PBYTES;     // 219,136 B
    cudaFuncSetAttribute(ft_kernel, cudaFuncAttributeMaxDynamicSharedMemorySize,
                         smem_bytes);

    {
        int total = 2 * nnz;
        pack_kernel<<<(total + 255) / 256, 256>>>(stm_idx, nstm_idx,
                                                  stm_val, nstm_val, nnz);
    }

    {
        const int nchunks = H / HCHUNK;                 // 4
        const int ppb = (B + POSBLKS - 1) / POSBLKS;    // 443
        dim3 grid(POSBLKS, nchunks);
        ft_kernel<<<grid, 512, smem_bytes>>>(W_ft, b_ft, W_out, B, F, H, ppb);
    }

    {
        const int nparts = (H / HCHUNK) * 2;            // 8
        out_kernel<<<(B + 127) / 128, 128>>>(b_out, (float*)d_out, B, nparts);
    }
}

// round 4
// speedup vs baseline: 1.9641x; 1.0446x over previous
#include <cuda_runtime.h>
#include <cuda_fp16.h>
#include <cstdint>

#define HCHUNK 128            // hidden units per chunk (H=512 -> 4 chunks)
#define PADH   132            // halves per feature row (264B, 8B-aligned)
#define NNZP   32             // features per position
#define MAX_B  16384
#define MAX_NNZ (MAX_B * NNZP)
#define POSBLKS 37            // 37 * 4 chunks = 148 CTAs = 1 per SM
#define TILE_P  32            // positions staged per smem pair tile

#define WBYTES   (768 * PADH * 2)              // fp16 weight tile bytes (202,752)
#define PBYTES   (2 * TILE_P * NNZP * 8)       // staged pair bytes (16,384)

// scratch (__device__ globals: allocation-free)
__device__ uint2 g_packed[2][MAX_NNZ];  // (byte_offset, value as half2(v,v)) per nnz/side
__device__ float g_partials[MAX_B * 4]; // [p][chunk] partial output dots
// ---------------------------------------------------------------------------
// Pack (feature -> smem byte offset, value as half2) pairs, 2 items per thread.
// int64-vs-int32 detection per block: viewing batch_row (row 0) as int32
// words, the odd words are all zero iff the data is int64.
__global__ void pack_kernel(const void* __restrict__ stm_idx,
                            const void* __restrict__ nstm_idx,
                            const float* __restrict__ stm_val,
                            const float* __restrict__ nstm_val,
                            int nnz) {
    __shared__ int s_is64;
    if (threadIdx.x == 0) {
        const int* words = (const int*)stm_idx;
        int nz = 0;
        #pragma unroll
        for (int k = 1; k <= 32; k++) nz |= words[64 * k + 33];
        s_is64 = (nz == 0) ? 1 : 0;
    }
    __syncthreads();
    const int is64 = s_is64;

    const int half_n = nnz >> 1;                       // pairs per side
    int i = blockIdx.x * blockDim.x + threadIdx.x;
    if (i >= 2 * half_n) return;
    const int side = (i >= half_n) ? 1 : 0;
    const int jp = side ? (i - half_n) : i;            // pair index
    const int j = 2 * jp;
    const void* idx = side ? nstm_idx : stm_idx;
    const float* val = side ? nstm_val : stm_val;

    int f0, f1;
    if (is64) {
        const longlong2 ff = ((const longlong2*)idx)[(((size_t)nnz + j) >> 1)];
        f0 = (int)ff.x; f1 = (int)ff.y;
    } else {
        const int2 ff = *(const int2*)((const int*)idx + (size_t)nnz + j);
        f0 = ff.x; f1 = ff.y;
    }
    const float2 vv = *(const float2*)(val + j);
    unsigned h0 = (unsigned)__half_as_ushort(__float2half(vv.x));
    unsigned h1 = (unsigned)__half_as_ushort(__float2half(vv.y));
    uint4 out;
    out.x = (unsigned)(f0 * (PADH * 2)); out.y = h0 | (h0 << 16);
    out.z = (unsigned)(f1 * (PADH * 2)); out.w = h1 | (h1 << 16);
    *(uint4*)(&g_packed[side][j]) = out;
}

// ---------------------------------------------------------------------------
// Feature transformer. grid = (POSBLKS, 4), block = 512, 1 CTA/SM.
// smem: fp16 weight tile [768 feat][128 units] + staged pair tile (both sides).
// One warp per position handles BOTH sides (64 features); stm/nstm outputs are
// combined per-lane before a single warp reduction.
extern __shared__ char s_raw[];

__global__ __launch_bounds__(512, 1)
void ft_kernel(const float* __restrict__ W_ft,
               const float* __restrict__ b_ft,
               const float* __restrict__ W_out,
               int B, int F, int H, int ppb) {
    __half* s_w = (__half*)s_raw;
    uint2*  s_pairs = (uint2*)(s_raw + WBYTES);

    const int chunk = blockIdx.y;
    const int h0 = chunk * HCHUNK;

    // Load tile: s_w[f*PADH + j] = half(W_ft[h0+j, f]).
    for (int idx = threadIdx.x; idx < F * (HCHUNK / 2); idx += blockDim.x) {
        int f  = idx % F;                  // consecutive threads -> coalesced LDG
        int jp = idx / F;
        float v0 = W_ft[(size_t)(h0 + 2 * jp) * F + f];
        float v1 = W_ft[(size_t)(h0 + 2 * jp + 1) * F + f];
        *(__half2*)(s_w + (size_t)f * PADH + 2 * jp) = __floats2half2_rn(v0, v1);
    }

    const int lane = threadIdx.x & 31;
    const int warp = threadIdx.x >> 5;

    const float4 bv  = *(const float4*)(b_ft  + h0 + 4 * lane);
    const float4 wo0 = *(const float4*)(W_out + h0 + 4 * lane);
    const float4 wo1 = *(const float4*)(W_out + H + h0 + 4 * lane);

    const char* sbl = (const char*)s_w + 8 * lane;
    const int p0 = blockIdx.x * ppb;
    const int p1 = min(p0 + ppb, B);

    for (int pt = p0; pt < p1; pt += TILE_P) {
        const int tp = min(TILE_P, p1 - pt);
        __syncthreads();   // previous tile consumed (covers tile load on 1st iter)
        {   // stage pair lists for this position tile (both sides), coalesced
            const int nvec = tp * (NNZP / 2);            // uint4 per side
            const uint4* src0 = (const uint4*)(g_packed[0] + (size_t)pt * NNZP);
            const uint4* src1 = (const uint4*)(g_packed[1] + (size_t)pt * NNZP);
            uint4* dst = (uint4*)s_pairs;
            for (int i = threadIdx.x; i < nvec; i += blockDim.x) {
                dst[i] = src0[i];
                dst[TILE_P * (NNZP / 2) + i] = src1[i];
            }
        }
        __syncthreads();

        for (int lp = warp; lp < tp; lp += 16) {
            const uint4* pk0 = (const uint4*)s_pairs + lp * (NNZP / 2);
            const uint4* pk1 = pk0 + TILE_P * (NNZP / 2);

            __half2 s01 = __float2half2_rn(0.f), s23 = s01;  // stm accums
            __half2 n01 = s01, n23 = s01;                    // nstm accums
            #pragma unroll
            for (int kk = 0; kk < NNZP / 2; kk++) {
                const uint4 pa = pk0[kk];                 // broadcast LDS.128
                const uint4 pb = pk1[kk];
                {
                    uint2 w = *(const uint2*)(sbl + pa.x);
                    const __half2 v = *(const __half2*)&pa.y;
                    s01 = __hfma2(v, *(const __half2*)&w.x, s01);
                    s23 = __hfma2(v, *(const __half2*)&w.y, s23);
                }
                {
                    uint2 w = *(const uint2*)(sbl + pa.z);
                    const __half2 v = *(const __half2*)&pa.w;
                    s01 = __hfma2(v, *(const __half2*)&w.x, s01);
                    s23 = __hfma2(v, *(const __half2*)&w.y, s23);
                }
                {
                    uint2 w = *(const uint2*)(sbl + pb.x);
                    const __half2 v = *(const __half2*)&pb.y;
                    n01 = __hfma2(v, *(const __half2*)&w.x, n01);
                    n23 = __hfma2(v, *(const __half2*)&w.y, n23);
                }
                {
                    uint2 w = *(const uint2*)(sbl + pb.z);
                    const __half2 v = *(const __half2*)&pb.w;
                    n01 = __hfma2(v, *(const __half2*)&w.x, n01);
                    n23 = __hfma2(v, *(const __half2*)&w.y, n23);
                }
            }

            const float2 fs01 = __half22float2(s01);
            const float2 fs23 = __half22float2(s23);
            const float2 fn01 = __half22float2(n01);
            const float2 fn23 = __half22float2(n23);
            float part = __saturatef(fs01.x + bv.x) * wo0.x
                       + __saturatef(fs01.y + bv.y) * wo0.y
                       + __saturatef(fs23.x + bv.z) * wo0.z
                       + __saturatef(fs23.y + bv.w) * wo0.w
                       + __saturatef(fn01.x + bv.x) * wo1.x
                       + __saturatef(fn01.y + bv.y) * wo1.y
                       + __saturatef(fn23.x + bv.z) * wo1.z
                       + __saturatef(fn23.y + bv.w) * wo1.w;
            #pragma unroll
            for (int o = 16; o; o >>= 1)
                part += __shfl_xor_sync(0xFFFFFFFFu, part, o);
            if (lane == 0)
                g_partials[(size_t)(pt + lp) * 4 + chunk] = part;
        }
    }
}

// ---------------------------------------------------------------------------
// Epilogue: one coalesced float4 per position, sum + bias + sigmoid.
__global__ void out_kernel(const float* __restrict__ b_out,
                           float* __restrict__ out, int B) {
    int p = blockIdx.x * blockDim.x + threadIdx.x;
    if (p >= B) return;
    const float4 q = *(const float4*)(g_partials + (size_t)p * 4);
    float s = b_out[0] + q.x + q.y + q.z + q.w;
    out[p] = 1.f / (1.f + expf(-s));
}

// ---------------------------------------------------------------------------
extern "C" void kernel_launch(void* const* d_in, const int* in_sizes, int n_in,
                              void* d_out, int out_size) {
    const void* stm_idx  = d_in[0];
    const void* nstm_idx = d_in[1];
    const float* stm_val  = (const float*)d_in[2];
    const float* nstm_val = (const float*)d_in[3];
    int w = 4;
    if (n_in >= 9 && in_sizes[4] == 1) w = 5;   // skip batch_size scalar
    const float* W_ft  = (const float*)d_in[w];
    const float* b_ft  = (const float*)d_in[w + 1];
    const float* W_out = (const float*)d_in[w + 2];
    const float* b_out = (const float*)d_in[w + 3];

    const int B   = out_size;
    const int H   = in_sizes[w + 1];
    const int F   = in_sizes[w] / H;
    const int nnz = in_sizes[2];

    const int smem_bytes = WBYTES + PBYTES;     // 219,136 B
    cudaFuncSetAttribute(ft_kernel, cudaFuncAttributeMaxDynamicSharedMemorySize,
                         smem_bytes);

    {
        int total = nnz;                        // 2 sides * (nnz/2) pair-threads
        pack_kernel<<<(total + 255) / 256, 256>>>(stm_idx, nstm_idx,
                                                  stm_val, nstm_val, nnz);
    }

    {
        const int nchunks = H / HCHUNK;                 // 4
        const int ppb = (B + POSBLKS - 1) / POSBLKS;    // 443
        dim3 grid(POSBLKS, nchunks);
        ft_kernel<<<grid, 512, smem_bytes>>>(W_ft, b_ft, W_out, B, F, H, ppb);
    }

    out_kernel<<<(B + 127) / 128, 128>>>(b_out, (float*)d_out, B);
}